// round 9
// baseline (speedup 1.0000x reference)
#include <cuda_runtime.h>
#include <cuda_bf16.h>

#define TPB 256
#define RPT 8          // anchors per thread (4 f32x2 lane-pairs)
#define NPK (RPT / 2)
#define MAXA 256       // smem GT capacity (A=64 here, +1 sentinel)

typedef unsigned long long u64;

// ---- f32x2 packed helpers (VERIFIED subset: add/fma only; no min/max!) ----
__device__ __forceinline__ u64 pk2(float lo, float hi) {
    u64 d;
    asm("mov.b64 %0, {%1, %2};" : "=l"(d) : "r"(__float_as_uint(lo)), "r"(__float_as_uint(hi)));
    return d;
}
__device__ __forceinline__ void upk2(u64 v, float& lo, float& hi) {
    unsigned a, b;
    asm("mov.b64 {%0, %1}, %2;" : "=r"(a), "=r"(b) : "l"(v));
    lo = __uint_as_float(a); hi = __uint_as_float(b);
}
__device__ __forceinline__ u64 add2(u64 a, u64 b) {
    u64 d; asm("add.rn.f32x2 %0, %1, %2;" : "=l"(d) : "l"(a), "l"(b)); return d;
}
__device__ __forceinline__ u64 fma2(u64 a, u64 b, u64 c) {
    u64 d; asm("fma.rn.f32x2 %0, %1, %2, %3;" : "=l"(d) : "l"(a), "l"(b), "l"(c)); return d;
}

__global__ __launch_bounds__(TPB)
void AssignClsLabel_kernel(const float4* __restrict__ anchors,
                           const float4* __restrict__ gts,
                           const int* __restrict__ counts,
                           const int* __restrict__ use_anchor_p,
                           float* __restrict__ out,
                           int N, int A, int blocksPerBatch) {
    // GT record: float4 (3*gy2, -3*gy1, gx2, -gx1) + packed u64 {-2ga,-2ga}
    __shared__ float4 sgc[MAXA + 1];
    __shared__ u64    sgn[MAXA + 1];
    __shared__ float  sredmax[TPB / 32], sredmin[TPB / 32];
    __shared__ int    scnt;

    const int b   = blockIdx.x / blocksPerBatch;
    const int blk = blockIdx.x - b * blocksPerBatch;
    const int cnt = counts[b];
    const int ua  = use_anchor_p ? use_anchor_p[0] : 1;
    const int tid = threadIdx.x;
    const int base = blk * (TPB * RPT) + tid;

    // ---- Load anchors; precompute scaled/negated corners + areas ----
    float y2s[RPT], y1n[RPT], x2v[RPT], x1n[RPT], ar[RPT], wm[RPT];
    float amax = -1e30f, amin = 1e30f;
    #pragma unroll
    for (int r = 0; r < RPT; r++) {
        int idx = base + r * TPB;
        // OOB sentinel: mins select GT values -> w = 4ga - (band path impossible,
        // since 4ga << 2*ar with ar=1) -> definite label 0, never in band.
        y2s[r] = 3.6e10f; y1n[r] = 3.6e10f; x2v[r] = 4e9f; x1n[r] = 4e9f; ar[r] = 1.f;
        wm[r] = -1e30f;
        if (idx < N) {
            float4 a = anchors[(size_t)b * N + idx];
            float y1, y2, x1, x2;
            if (ua) {
                y1 = a.x - 0.5f * a.z;  y2 = y1 + a.z;
                x1 = a.y - 0.5f * a.w;  x2 = x1 + a.w;
                ar[r] = __fmul_rn(a.z, a.w);
            } else {
                y1 = a.x; x1 = a.y; y2 = a.z; x2 = a.w;
                ar[r] = __fmul_rn(__fsub_rn(y2, y1), __fsub_rn(x2, x1));
            }
            y2s[r] = 3.0f * y2;  y1n[r] = -3.0f * y1;   // fast path approx; band covers
            x2v[r] = x2;         x1n[r] = -x1;
            amax = fmaxf(amax, ar[r]);
            amin = fminf(amin, ar[r]);
        }
    }

    // ---- Block-wide anchor-area min/max for exact GT pruning ----
    #pragma unroll
    for (int off = 16; off > 0; off >>= 1) {
        amax = fmaxf(amax, __shfl_xor_sync(0xffffffffu, amax, off));
        amin = fminf(amin, __shfl_xor_sync(0xffffffffu, amin, off));
    }
    if ((tid & 31) == 0) { sredmax[tid >> 5] = amax; sredmin[tid >> 5] = amin; }
    if (tid == 0) scnt = 0;
    __syncthreads();
    amax = sredmax[0]; amin = sredmin[0];
    #pragma unroll
    for (int w = 1; w < TPB / 32; w++) {
        amax = fmaxf(amax, sredmax[w]);
        amin = fminf(amin, sredmin[w]);
    }
    // iou>=0.5 requires area/2 <= ga <= 2*area; 0.5% slack >> fp rounding,
    // so the prune only removes provably-unmatchable GTs (labels unchanged).
    const float gaHi = 2.01f * amax;
    const float gaLo = amin * (1.0f / 2.01f);

    // ---- Stage + compact matchable GTs ----
    for (int g = tid; g < cnt; g += TPB) {
        float4 v = gts[(size_t)b * A + g];           // (gy1, gx1, gy2, gx2)
        float ga = __fmul_rn(__fsub_rn(v.z, v.x), __fsub_rn(v.w, v.y));
        if (ga <= gaHi && ga >= gaLo) {
            int p = atomicAdd(&scnt, 1);
            sgc[p] = make_float4(3.0f * v.z, -3.0f * v.x, v.w, -v.y);
            float g2 = -2.0f * ga;
            sgn[p] = pk2(g2, g2);
        }
    }
    __syncthreads();
    const int m = scnt;
    if (m > 0 && tid == 0) { sgc[m] = sgc[0]; sgn[m] = sgn[0]; }
    __syncthreads();

    // ---- Main loop ----
    // dy3  = min(3y2,3gy2) + min(-3y1,-3gy1)          (scalar FMNMX + add2)
    // dypp = dy3 + |dy3| = 2*max(dy3,0)  (exact)      (and.b64 + add2)
    // dx   = min(x2,gx2) + min(-x1,-gx1)
    // w    = dypp*dx - 2ga   ;  positive label test: w >= 2*ar (<=> 3*inter >= ar+ga)
    const u64 ABSM = 0x7FFFFFFF7FFFFFFFull;
    float4 gc = sgc[0];
    u64    gn = sgn[0];
    #pragma unroll 2
    for (int g = 0; g < m; g++) {
        const float4 gcc = gc;
        const u64    gnc = gn;
        gc = sgc[g + 1]; gn = sgn[g + 1];            // sentinel-padded prefetch
        #pragma unroll
        for (int j = 0; j < NPK; j++) {
            const int r0 = 2 * j, r1 = 2 * j + 1;
            float a0 = fminf(y2s[r0], gcc.x), a1 = fminf(y2s[r1], gcc.x);
            float b0 = fminf(y1n[r0], gcc.y), b1 = fminf(y1n[r1], gcc.y);
            u64 dy3  = add2(pk2(a0, a1), pk2(b0, b1));
            u64 dypp = add2(dy3, dy3 & ABSM);        // 2*max(dy3,0), exact
            float c0 = fminf(x2v[r0], gcc.z), c1 = fminf(x2v[r1], gcc.z);
            float d0 = fminf(x1n[r0], gcc.w), d1 = fminf(x1n[r1], gcc.w);
            u64 dx   = add2(pk2(c0, c1), pk2(d0, d1));
            u64 w    = fma2(dypp, dx, gnc);          // dx<0 => w <= -2ga, safely negative
            float w0, w1;
            upk2(w, w0, w1);
            wm[r0] = fmaxf(wm[r0], w0);
            wm[r1] = fmaxf(wm[r1], w1);
        }
    }

    // ---- Classify; band hits (rare) -> literal bit-exact fallback ----
    #pragma unroll
    for (int r = 0; r < RPT; r++) {
        int idx = base + r * TPB;
        if (idx >= N) continue;
        float thr  = 2.0f * ar[r];
        // band = 2e-5*(ar+gaHi): >=40x the fast-path chain + threshold slack.
        float band = 2e-5f * (ar[r] + gaHi);
        float lab;
        if (wm[r] >= thr + band) {
            lab = 1.0f;
        } else if (wm[r] <= thr - band) {
            lab = 0.0f;
        } else {
            // Exact literal reference replay for this anchor.
            lab = 0.0f;
            float4 a = anchors[(size_t)b * N + idx];
            float y1, y2, x1, x2, area;
            if (ua) {
                y1 = a.x - 0.5f * a.z;  y2 = y1 + a.z;
                x1 = a.y - 0.5f * a.w;  x2 = x1 + a.w;
                area = __fmul_rn(a.z, a.w);
            } else {
                y1 = a.x; x1 = a.y; y2 = a.z; x2 = a.w;
                area = __fmul_rn(__fsub_rn(y2, y1), __fsub_rn(x2, x1));
            }
            for (int g = 0; g < cnt; g++) {
                float4 v2 = gts[(size_t)b * A + g];
                float ga2 = __fmul_rn(__fsub_rn(v2.z, v2.x), __fsub_rn(v2.w, v2.y));
                float yy1 = fminf(fmaxf(y1, v2.x), v2.z);
                float yy2 = fminf(fmaxf(y2, v2.x), v2.z);
                float xx1 = fminf(fmaxf(x1, v2.y), v2.w);
                float xx2 = fminf(fmaxf(x2, v2.y), v2.w);
                float it  = __fmul_rn(__fsub_rn(yy2, yy1), __fsub_rn(xx2, xx1));
                float uni = __fsub_rn(__fadd_rn(area, ga2), it);
                if (__fdiv_rn(it, uni) >= 0.5f) { lab = 1.0f; break; }
            }
        }
        out[(size_t)b * N + idx] = lab;
    }
}

extern "C" void kernel_launch(void* const* d_in, const int* in_sizes, int n_in,
                              void* d_out, int out_size) {
    // Bind by size signature: anchors = largest; gts = 2nd largest;
    // of the rest, counts = larger (B elems), use_anchor = smaller (optional).
    int ia = 0;
    for (int i = 1; i < n_in; i++) if (in_sizes[i] > in_sizes[ia]) ia = i;
    int ig = -1;
    for (int i = 0; i < n_in; i++) {
        if (i == ia) continue;
        if (ig < 0 || in_sizes[i] > in_sizes[ig]) ig = i;
    }
    int ic = -1, iu = -1;
    for (int i = 0; i < n_in; i++) {
        if (i == ia || i == ig) continue;
        if (ic < 0) ic = i;
        else if (in_sizes[i] > in_sizes[ic]) { iu = ic; ic = i; }
        else iu = i;
    }

    const float4* anchors = (const float4*)d_in[ia];
    const float4* gts     = (const float4*)d_in[ig];
    const int*    counts  = (const int*)d_in[ic];
    const int*    ua_ptr  = (iu >= 0) ? (const int*)d_in[iu] : (const int*)0;
    float* out = (float*)d_out;

    const int B = in_sizes[ic];
    const int A = in_sizes[ig] / (4 * B);
    const int N = in_sizes[ia] / (4 * B);

    const int anchorsPerBlock = TPB * RPT;
    const int blocksPerBatch = (N + anchorsPerBlock - 1) / anchorsPerBlock;
    const int grid = B * blocksPerBatch;

    AssignClsLabel_kernel<<<grid, TPB>>>(anchors, gts, counts, ua_ptr, out,
                                         N, A, blocksPerBatch);
}